// round 14
// baseline (speedup 1.0000x reference)
#include <cuda_runtime.h>
#include <cuda_fp16.h>
#include <cstdint>

// ---------------------------------------------------------------------------
// Problem constants  (R13 champion base + 3-stage x ring)
// ---------------------------------------------------------------------------
#define OUT_N    8192
#define IN_K     8192
#define BATCH    64
#define TILE_N   128                  // W rows per CTA
#define KSPLIT   8
#define NGRPS    (OUT_N / TILE_N)     // 64
#define NSUB     16                   // k64 subchunks per CTA (k total 1024)
#define NCH      8                    // k128 scale-chunks per CTA
#define NTHREADS 256

// SMEM layout (bytes). Rows hold 64 halfs = 128 B, padded stride 144 B
// (odd multiple of 16 B -> conflict-free ldmatrix over 8-row groups)
#define RS          144
#define W_BYTES     (TILE_N * RS)          // 18432  (x2 stages)
#define X_BYTES     (BATCH * RS)           // 9216   (x3 stages)
#define X_OFF       (2 * W_BYTES)          // 36864
#define SCALE_OFF   (X_OFF + 3 * X_BYTES)  // 64512
#define SCALE_BYTES (NCH * TILE_N * 4)     // 4096
#define SMEM_TOTAL  (SCALE_OFF + SCALE_BYTES)  // 68608 -> 3 CTAs/SM (205.8KB)

// Static scratch: x converted to fp16 (1 MiB)
__device__ __half g_xh[BATCH * IN_K];

// ---------------------------------------------------------------------------
// PTX helpers (family-portable: ptxas target is sm_103, no tcgen05)
// ---------------------------------------------------------------------------
__device__ __forceinline__ void ldsm_x4(uint32_t& r0, uint32_t& r1, uint32_t& r2,
                                        uint32_t& r3, uint32_t addr) {
    asm volatile("ldmatrix.sync.aligned.m8n8.x4.shared.b16 {%0,%1,%2,%3}, [%4];"
                 : "=r"(r0), "=r"(r1), "=r"(r2), "=r"(r3) : "r"(addr));
}
__device__ __forceinline__ void mma_16816(float* c, uint32_t a0, uint32_t a1,
                                          uint32_t a2, uint32_t a3,
                                          uint32_t b0, uint32_t b1) {
    asm volatile(
        "mma.sync.aligned.m16n8k16.row.col.f32.f16.f16.f32 "
        "{%0,%1,%2,%3},{%4,%5,%6,%7},{%8,%9},{%0,%1,%2,%3};"
        : "+f"(c[0]), "+f"(c[1]), "+f"(c[2]), "+f"(c[3])
        : "r"(a0), "r"(a1), "r"(a2), "r"(a3), "r"(b0), "r"(b1));
}
// .ca: co-resident CTAs (same k-group) re-read identical x windows -> L1 hits
__device__ __forceinline__ void cp_async16_ca(uint32_t dst, const void* src) {
    asm volatile("cp.async.ca.shared.global [%0], [%1], 16;"
                 :: "r"(dst), "l"(src) : "memory");
}
__device__ __forceinline__ void cp_commit() {
    asm volatile("cp.async.commit_group;" ::: "memory");
}

// ---------------------------------------------------------------------------
// Kernel 1: convert x fp32->fp16 AND zero-init out. 4 independent float4 per
// thread (MLP=4) so DRAM latency overlaps. 128 blocks x 256 thr x 4 = 131072.
// ---------------------------------------------------------------------------
__global__ __launch_bounds__(256) void prep_kernel(const float* __restrict__ x,
                                                   float* __restrict__ out) {
    int base = blockIdx.x * 256 + threadIdx.x;
    #pragma unroll
    for (int k = 0; k < 4; k++) {
        int i = base + k * 32768;
        float4 v = reinterpret_cast<const float4*>(x)[i];
        __half2 h01 = __floats2half2_rn(v.x, v.y);
        __half2 h23 = __floats2half2_rn(v.z, v.w);
        uint2 o;
        o.x = *reinterpret_cast<uint32_t*>(&h01);
        o.y = *reinterpret_cast<uint32_t*>(&h23);
        reinterpret_cast<uint2*>(g_xh)[i] = o;
        reinterpret_cast<float4*>(out)[i] = make_float4(0.f, 0.f, 0.f, 0.f);
    }
}

// ---------------------------------------------------------------------------
// Kernel 2: int4-dequant GEMM (mma.sync). W double-buffer + x 3-stage ring.
// Grid = 512 CTAs: bid & 63 = n-group (128 W rows), bid >> 6 = k-group.
// Warp layout 2(m) x 4(n): warp owns 32 batch rows x 32 output cols.
// x is issued TWO subs ahead (wait_group 1 in steady state) so each transfer
// has ~2 MMA phases (>L2 latency) to land before its consuming barrier.
// ---------------------------------------------------------------------------
__global__ __launch_bounds__(NTHREADS, 3)
void dq_gemm_kernel(const int*   __restrict__ packed,
                    const float* __restrict__ scales,
                    float*       __restrict__ out)
{
    extern __shared__ __align__(16) char dsm[];
    const uint32_t sb = (uint32_t)__cvta_generic_to_shared(dsm);
    float* sScale = reinterpret_cast<float*>(dsm + SCALE_OFF);

    const int tid  = threadIdx.x;
    const int wid  = tid >> 5;
    const int lane = tid & 31;
    const int mh   = wid & 1;          // batch half
    const int ng   = wid >> 1;         // 32-col group
    const int n0   = (blockIdx.x & 63) * TILE_N;
    const int kg   = blockIdx.x >> 6;  // 0..7
    const int ks0  = kg * NSUB;        // global k64-subchunk base

    float acc[2][4][4];
    #pragma unroll
    for (int m = 0; m < 2; m++)
        #pragma unroll
        for (int n = 0; n < 4; n++)
            #pragma unroll
            for (int j = 0; j < 4; j++) acc[m][n][j] = 0.f;

    const uint4* pk4 = reinterpret_cast<const uint4*>(packed); // row stride 1024
    const uint32_t c1032b = 0x64086408u;                       // half2(1032,1032)
    const __half2 c1032 = *reinterpret_cast<const __half2*>(&c1032b);

    // ---- stage the scale table once: [NCH][TILE_N], float4-vectorized -----
    {
        int row = tid >> 1;                      // 0..127
        int c4  = tid & 1;                       // which float4 of the row
        float4 f = *reinterpret_cast<const float4*>(
            scales + (size_t)(n0 + row) * 64 + kg * NCH + c4 * 4);
        sScale[(c4 * 4 + 0) * TILE_N + row] = f.x;
        sScale[(c4 * 4 + 1) * TILE_N + row] = f.y;
        sScale[(c4 * 4 + 2) * TILE_N + row] = f.z;
        sScale[(c4 * 4 + 3) * TILE_N + row] = f.w;
    }

    // ---- packed-W register prefetch (one k64 sub = 1024 uint4 = 4/thread) -
    uint4 pv[4];
    auto prefetch = [&](int ks) {
        #pragma unroll
        for (int j = 0; j < 4; j++) {
            int u = tid + (j << 8);                  // 0..1023
            int row = u >> 3, kv = u & 7;
            pv[j] = pk4[(size_t)(n0 + row) * 1024 + ks * 8 + kv];
        }
    };

    // ---- x tile cp.async into ring stage xs (512 x 16B = 2/thread) --------
    auto stage_x = [&](int ks, int xs) {
        const uint32_t xb = sb + X_OFF + xs * X_BYTES;
        #pragma unroll
        for (int j = 0; j < 2; j++) {
            int u = tid + (j << 8);                  // 0..511
            int b = u >> 3, kv = u & 7;
            cp_async16_ca(xb + b * RS + kv * 16,
                          &g_xh[(size_t)b * IN_K + ks * 64 + kv * 8]);
        }
        cp_commit();
    };

    // dequant pv (subchunk sub) -> W buffer s (4 x STS.128 / thread)
    auto dequant_sts = [&](int s, int sub) {
        const uint32_t stage = sb + s * W_BYTES;
        const int lch = sub >> 1;                    // k128 scale chunk
        #pragma unroll
        for (int j = 0; j < 4; j++) {
            int u = tid + (j << 8);
            int row = u >> 3, kv = u & 7;
            __half2 s2 = __float2half2_rn(sScale[lch * TILE_N + row]);
            uint32_t w[4] = { pv[j].x, pv[j].y, pv[j].z, pv[j].w };
            uint32_t o[4];
            #pragma unroll
            for (int q = 0; q < 4; q++) {
                uint32_t t = ((w[q] * 0x1001u) & 0x000F000Fu) | 0x64006400u;
                __half2 hv = __hmul2(__hsub2(*reinterpret_cast<__half2*>(&t), c1032), s2);
                o[q] = *reinterpret_cast<uint32_t*>(&hv);
            }
            asm volatile("st.shared.v4.b32 [%0], {%1,%2,%3,%4};"
                         :: "r"(stage + row * RS + kv * 16),
                            "r"(o[0]), "r"(o[1]), "r"(o[2]), "r"(o[3]) : "memory");
        }
    };

    // ---- prologue ---------------------------------------------------------
    prefetch(ks0);                 // pv = packed[sub 0]
    stage_x(ks0, 0);               // x[0] -> ring 0  (group 1)
    stage_x(ks0 + 1, 1);           // x[1] -> ring 1  (group 2)
    __syncthreads();               // sScale visible to all
    dequant_sts(0, 0);             // W[0] STS -> W stage 0
    prefetch(ks0 + 1);             // pv = packed[sub 1]

    // ring indices kept as counters (no % in the hot loop)
    int xs_r = 0;                  // ring slot of x[sub]
    int xs_w = 2;                  // ring slot for x[sub+2]

    // Invariant at iteration entry (sub, s = sub&1):
    //   x[sub] is the OLDEST pending-or-done cp.async group (issued 2 ago);
    //   W[sub] STS issued into W stage s; pv = packed[sub+1].
    for (int sub = 0; sub < NSUB; sub++) {
        const int s = sub & 1;

        // x[sub] complete: allow 1 newer group (x[sub+1]) to stay in flight
        if (sub + 1 < NSUB)
            asm volatile("cp.async.wait_group 1;" ::: "memory");
        else
            asm volatile("cp.async.wait_group 0;" ::: "memory");
        __syncthreads();           // W[sub]/x[sub] visible; W stage s^1 free;
                                   // x ring slot xs_w's prior readers done

        if (sub + 1 < NSUB) {
            dequant_sts(s ^ 1, sub + 1);              // W[sub+1] (other buffer)
            if (sub + 2 < NSUB) {
                stage_x(ks0 + sub + 2, xs_w);         // x[sub+2] in flight
                prefetch(ks0 + sub + 2);              // pv = packed[sub+2]
            }
        }

        // ---- MMA(sub): 4 k16 tiles, warp tile 32(m) x 32(n) ---------------
        const uint32_t wbase = sb + s * W_BYTES;
        const uint32_t xbase = sb + X_OFF + xs_r * X_BYTES;
        #pragma unroll
        for (int kt = 0; kt < 4; kt++) {
            uint32_t b[4][2];             // [nt][b0,b1]
            #pragma unroll
            for (int np = 0; np < 2; np++) {
                int br = ng * 32 + np * 16 + ((lane >> 4) & 1) * 8 + (lane & 7);
                int bc = kt * 16 + ((lane >> 3) & 1) * 8;
                ldsm_x4(b[np*2][0], b[np*2][1], b[np*2+1][0], b[np*2+1][1],
                        wbase + (uint32_t)(br * RS + bc * 2));
            }
            #pragma unroll
            for (int mt = 0; mt < 2; mt++) {
                uint32_t a0, a1, a2, a3;
                int ar = mh * 32 + mt * 16 + (lane & 15);
                int ac = kt * 16 + (lane >> 4) * 8;
                ldsm_x4(a0, a1, a2, a3, xbase + (uint32_t)(ar * RS + ac * 2));
                #pragma unroll
                for (int nt = 0; nt < 4; nt++)
                    mma_16816(acc[mt][nt], a0, a1, a2, a3, b[nt][0], b[nt][1]);
            }
        }

        // advance ring counters
        xs_r = (xs_r == 2) ? 0 : xs_r + 1;
        xs_w = (xs_w == 2) ? 0 : xs_w + 1;
    }

    // ---- epilogue: vectorized float2 atomics (k-split merge) --------------
    #pragma unroll
    for (int mt = 0; mt < 2; mt++) {
        #pragma unroll
        for (int nt = 0; nt < 4; nt++) {
            int m = mh * 32 + mt * 16 + (lane >> 2);
            int n = n0 + ng * 32 + nt * 8 + (lane & 3) * 2;
            atomicAdd(reinterpret_cast<float2*>(&out[(size_t)m * OUT_N + n]),
                      make_float2(acc[mt][nt][0], acc[mt][nt][1]));
            atomicAdd(reinterpret_cast<float2*>(&out[(size_t)(m + 8) * OUT_N + n]),
                      make_float2(acc[mt][nt][2], acc[mt][nt][3]));
        }
    }
}

// ---------------------------------------------------------------------------
extern "C" void kernel_launch(void* const* d_in, const int* in_sizes, int n_in,
                              void* d_out, int out_size) {
    const float* x      = (const float*)d_in[0];
    const int*   packed = (const int*)d_in[1];
    const float* scales = (const float*)d_in[2];
    float*       out    = (float*)d_out;

    cudaFuncSetAttribute(dq_gemm_kernel,
                         cudaFuncAttributeMaxDynamicSharedMemorySize, SMEM_TOTAL);

    prep_kernel<<<128, 256>>>(x, out);
    dq_gemm_kernel<<<NGRPS * KSPLIT, NTHREADS, SMEM_TOTAL>>>(packed, scales, out);
}